// round 6
// baseline (speedup 1.0000x reference)
#include <cuda_runtime.h>
#include <cuda_bf16.h>
#include <math.h>
#include <stdint.h>

#define B_    2
#define NB_   512
#define L_    64
#define H_    8
#define DH_   64
#define C_    512
#define C3_   1536
#define MROWS 65536          // B*NB*L
#define BNB   1024           // B*NB
#define NBLL  2097152        // NB*L*L

// ---------------- static scratch (no allocations allowed) ----------------
__device__ float g_qkv   [100663296];  // [MROWS][1536] fp32
__device__ float g_gate  [16777216];   // [H][NB][L][L]
__device__ float g_smask [2097152];    // [NB][L][L]   bias3 + (mask?0:-1e30)
__device__ float g_gblock[524288];     // [MROWS][H]
__device__ float g_vblock[524288];     // [BNB][512]
__device__ float g_bnode [524288];     // [BNB][512]
__device__ __nv_bfloat16 g_xh[33554432];   // x hi  [MROWS][512]
__device__ __nv_bfloat16 g_xl[33554432];   // x lo
__device__ __nv_bfloat16 g_mh[33554432];   // xmid hi
__device__ __nv_bfloat16 g_ml[33554432];   // xmid lo
__device__ __nv_bfloat16 g_wqh[786432];    // w_qkv^T hi [1536][512]
__device__ __nv_bfloat16 g_wql[786432];
__device__ __nv_bfloat16 g_wph[262144];    // w_proj^T hi [512][512]
__device__ __nv_bfloat16 g_wpl[262144];

// =================== PTX helpers (baseline ISA only: sm_80+) ===================
__device__ __forceinline__ uint32_t s2u(const void* p) {
    return (uint32_t)__cvta_generic_to_shared(p);
}
__device__ __forceinline__ void cp16(uint32_t dst, const void* src) {
    asm volatile("cp.async.cg.shared.global [%0], [%1], 16;" :: "r"(dst), "l"(src));
}
#define LDSM4(r, a) \
    asm volatile("ldmatrix.sync.aligned.m8n8.x4.shared.b16 {%0,%1,%2,%3}, [%4];" \
        : "=r"((r)[0]), "=r"((r)[1]), "=r"((r)[2]), "=r"((r)[3]) : "r"(a))
#define MMA16816(c, a, b) \
    asm volatile("mma.sync.aligned.m16n8k16.row.col.f32.bf16.bf16.f32 " \
        "{%0,%1,%2,%3}, {%4,%5,%6,%7}, {%8,%9}, {%0,%1,%2,%3};" \
        : "+f"((c)[0]), "+f"((c)[1]), "+f"((c)[2]), "+f"((c)[3]) \
        : "r"((a)[0]), "r"((a)[1]), "r"((a)[2]), "r"((a)[3]), "r"((b)[0]), "r"((b)[1]))

// =================== bf16x2-split GEMM via HMMA mma.sync ===================
// C[M,N] = A@W^T + bias. CTA tile 256(M) x 128(N), K chunks of 64, double buffer.
// Warp tile 64x64, 8 warps as 4(M) x 2(N).
// 3 passes: hi*hi + hi*lo + lo*hi into fp32 accumulators.
// Stage layout: Ah[256x64] Al Bh[128x64] Bl, 128B rows, XOR-swizzle ch^(row&7).
#define A_TILE 32768
#define B_TILE 16384
#define STAGE_BYTES 98304
#define GSMEM (2 * STAGE_BYTES)

__device__ __forceinline__ void gemm_load_stage(
    uint32_t st, int tid, int kc,
    const __nv_bfloat16* __restrict__ A_h, const __nv_bfloat16* __restrict__ A_l,
    const __nv_bfloat16* __restrict__ B_h, const __nv_bfloat16* __restrict__ B_l)
{
    // A tiles: 256 rows x 8 chunks = 2048 -> 8 iters of 256
    #pragma unroll
    for (int r = 0; r < 8; r++) {
        int idx = r * 256 + tid;
        int row = idx >> 3, ch = idx & 7;
        uint32_t d = row * 128 + ((ch ^ (row & 7)) << 4);
        const __nv_bfloat16* s = (const __nv_bfloat16*)((size_t)row * 1024) ;
        (void)s;
        cp16(st + d,          A_h + (size_t)row * 512 + kc * 64 + ch * 8);
        cp16(st + A_TILE + d, A_l + (size_t)row * 512 + kc * 64 + ch * 8);
    }
    // B tiles: 128 rows x 8 chunks = 1024 -> 4 iters of 256
    #pragma unroll
    for (int r = 0; r < 4; r++) {
        int idx = r * 256 + tid;
        int row = idx >> 3, ch = idx & 7;
        uint32_t d = row * 128 + ((ch ^ (row & 7)) << 4);
        cp16(st + 2 * A_TILE + d,          B_h + (size_t)row * 512 + kc * 64 + ch * 8);
        cp16(st + 2 * A_TILE + B_TILE + d, B_l + (size_t)row * 512 + kc * 64 + ch * 8);
    }
    asm volatile("cp.async.commit_group;" ::: "memory");
}

__global__ void __launch_bounds__(256, 1)
gemm_bf16x2_kernel(const __nv_bfloat16* __restrict__ Ah, const __nv_bfloat16* __restrict__ Al,
                   const __nv_bfloat16* __restrict__ Bh, const __nv_bfloat16* __restrict__ Bl,
                   const float* __restrict__ bias, float* __restrict__ C, int ldC)
{
    extern __shared__ __align__(1024) char smem[];
    uint32_t sb = s2u(smem);
    int tid = threadIdx.x;
    int warp = tid >> 5, lane = tid & 31;
    int m0 = blockIdx.y * 256, n0 = blockIdx.x * 128;
    int wm = (warp & 3) * 64, wn = (warp >> 2) * 64;

    const __nv_bfloat16* pAh = Ah + (size_t)m0 * 512;
    const __nv_bfloat16* pAl = Al + (size_t)m0 * 512;
    const __nv_bfloat16* pBh = Bh + (size_t)n0 * 512;
    const __nv_bfloat16* pBl = Bl + (size_t)n0 * 512;

    float acc[4][8][4];
    #pragma unroll
    for (int i = 0; i < 4; i++)
        #pragma unroll
        for (int j = 0; j < 8; j++)
            #pragma unroll
            for (int t = 0; t < 4; t++) acc[i][j][t] = 0.f;

    // ldmatrix geometry
    int aRow[4], bRow[4];
    #pragma unroll
    for (int mi = 0; mi < 4; mi++) aRow[mi] = wm + mi * 16 + (lane & 15);
    #pragma unroll
    for (int nj = 0; nj < 4; nj++) bRow[nj] = wn + nj * 16 + (lane & 7) + ((lane >> 4) << 3);
    int aSel = lane >> 4;          // +8 in k
    int bSel = (lane >> 3) & 1;

    gemm_load_stage(sb, tid, 0, pAh, pAl, pBh, pBl);

    for (int kc = 0; kc < 8; kc++) {
        if (kc + 1 < 8) {
            gemm_load_stage(sb + ((kc + 1) & 1) * STAGE_BYTES, tid, kc + 1,
                            pAh, pAl, pBh, pBl);
            asm volatile("cp.async.wait_group 1;" ::: "memory");
        } else {
            asm volatile("cp.async.wait_group 0;" ::: "memory");
        }
        __syncthreads();

        uint32_t stA_h = sb + (kc & 1) * STAGE_BYTES;
        uint32_t stA_l = stA_h + A_TILE;
        uint32_t stB_h = stA_h + 2 * A_TILE;
        uint32_t stB_l = stB_h + B_TILE;

        #pragma unroll
        for (int kk = 0; kk < 4; kk++) {
            uint32_t bh[4][4], bl[4][4];
            int chB = kk * 2 + bSel;
            #pragma unroll
            for (int nj = 0; nj < 4; nj++) {
                uint32_t bd = bRow[nj] * 128 + ((chB ^ (bRow[nj] & 7)) << 4);
                LDSM4(bh[nj], stB_h + bd);
                LDSM4(bl[nj], stB_l + bd);
            }
            int chA = kk * 2 + aSel;
            #pragma unroll
            for (int mi = 0; mi < 4; mi++) {
                uint32_t ah[4], al[4];
                uint32_t ad = aRow[mi] * 128 + ((chA ^ (aRow[mi] & 7)) << 4);
                LDSM4(ah, stA_h + ad);
                LDSM4(al, stA_l + ad);
                #pragma unroll
                for (int nj = 0; nj < 4; nj++) {
                    MMA16816(acc[mi][nj * 2 + 0], ah, (bh[nj] + 0));
                    MMA16816(acc[mi][nj * 2 + 1], ah, (bh[nj] + 2));
                    MMA16816(acc[mi][nj * 2 + 0], ah, (bl[nj] + 0));
                    MMA16816(acc[mi][nj * 2 + 1], ah, (bl[nj] + 2));
                    MMA16816(acc[mi][nj * 2 + 0], al, (bh[nj] + 0));
                    MMA16816(acc[mi][nj * 2 + 1], al, (bh[nj] + 2));
                }
            }
        }
        __syncthreads();
    }

    // epilogue: +bias, fp32 store
    #pragma unroll
    for (int mi = 0; mi < 4; mi++) {
        int row = m0 + wm + mi * 16 + (lane >> 2);
        #pragma unroll
        for (int ni = 0; ni < 8; ni++) {
            int col = n0 + wn + ni * 8 + (lane & 3) * 2;
            float2 bv = *(const float2*)(bias + col);
            float2 o0, o1;
            o0.x = acc[mi][ni][0] + bv.x; o0.y = acc[mi][ni][1] + bv.y;
            o1.x = acc[mi][ni][2] + bv.x; o1.y = acc[mi][ni][3] + bv.y;
            *(float2*)(C + (size_t)row * ldC + col) = o0;
            *(float2*)(C + (size_t)(row + 8) * ldC + col) = o1;
        }
    }
}

// ============ convert x -> bf16 hi/lo, fused g_block sigmoid ============
__global__ void __launch_bounds__(256) convx_kernel(const float* __restrict__ x,
    const float* __restrict__ wblk, const float* __restrict__ bblk)
{
    __shared__ __align__(16) float swt[8][512];   // wblk transposed
    int tid = threadIdx.x;
    for (int idx = tid; idx < 4096; idx += 256)
        swt[idx & 7][idx >> 3] = wblk[idx];
    __syncthreads();
    int wid = tid >> 5, lane = tid & 31;
    int row = blockIdx.x * 8 + wid;
    const float* xr = x + (size_t)row * 512;
    float acc[8] = {};
    #pragma unroll
    for (int i = 0; i < 4; i++) {
        int c = i * 128 + lane * 4;
        float4 v = *(const float4*)(xr + c);
        float vv[4] = {v.x, v.y, v.z, v.w};
        __nv_bfloat16 hh[4]; __nv_bfloat16 ll[4];
        #pragma unroll
        for (int j = 0; j < 4; j++) {
            hh[j] = __float2bfloat16(vv[j]);
            ll[j] = __float2bfloat16(vv[j] - __bfloat162float(hh[j]));
        }
        __nv_bfloat162 p0; p0.x = hh[0]; p0.y = hh[1];
        __nv_bfloat162 p1; p1.x = hh[2]; p1.y = hh[3];
        __nv_bfloat162 q0; q0.x = ll[0]; q0.y = ll[1];
        __nv_bfloat162 q1; q1.x = ll[2]; q1.y = ll[3];
        size_t o = (size_t)row * 512 + c;
        *(__nv_bfloat162*)(g_xh + o) = p0; *(__nv_bfloat162*)(g_xh + o + 2) = p1;
        *(__nv_bfloat162*)(g_xl + o) = q0; *(__nv_bfloat162*)(g_xl + o + 2) = q1;
        #pragma unroll
        for (int h = 0; h < 8; h++) {
            float4 wv = *(const float4*)(&swt[h][c]);
            acc[h] += vv[0] * wv.x + vv[1] * wv.y + vv[2] * wv.z + vv[3] * wv.w;
        }
    }
    #pragma unroll
    for (int m = 16; m; m >>= 1)
        #pragma unroll
        for (int h = 0; h < 8; h++) acc[h] += __shfl_xor_sync(0xffffffffu, acc[h], m);
    if (lane == 0) {
        #pragma unroll
        for (int h = 0; h < 8; h++)
            g_gblock[row * 8 + h] = 1.f / (1.f + __expf(-(acc[h] + bblk[h])));
    }
}

// ============ weight transpose + bf16 split: W[K][N] -> T[N][K] ============
__global__ void wsplit_kernel(const float* __restrict__ W,
    __nv_bfloat16* __restrict__ Th, __nv_bfloat16* __restrict__ Tl, int Kd, int Nd)
{
    __shared__ float tile[32][33];
    int tx = threadIdx.x & 31, ty = threadIdx.x >> 5;
    int n0 = blockIdx.x * 32, k0 = blockIdx.y * 32;
    #pragma unroll
    for (int r = 0; r < 4; r++)
        tile[ty + r * 8][tx] = W[(size_t)(k0 + ty + r * 8) * Nd + n0 + tx];
    __syncthreads();
    #pragma unroll
    for (int r = 0; r < 4; r++) {
        int n = ty + r * 8;
        float v = tile[tx][n];
        __nv_bfloat16 h = __float2bfloat16(v);
        size_t o = (size_t)(n0 + n) * Kd + k0 + tx;
        Th[o] = h;
        Tl[o] = __float2bfloat16(v - __bfloat162float(h));
    }
}

// ================= prep: fixed mask, bias diag, gate MLP =================
// 256 threads = 4 q-rows of 64 k each
__global__ void __launch_bounds__(256) prep_kernel(const int* __restrict__ mask,
                            const float* __restrict__ ef,
                            const float* __restrict__ w1, const float* __restrict__ b1,
                            const float* __restrict__ w2, const float* __restrict__ b2)
{
    __shared__ float sw1[64], sb1[16], sw2[128], sb2[8];
    __shared__ int ssum[4];
    int t = threadIdx.x;
    int r = t >> 6;                 // row 0..3
    int kk = t & 63;                // k index
    int nbq = blockIdx.x * 4 + r;   // nb*64+q
    int q   = nbq & 63;
    if (t < 64) sw1[t] = w1[t];
    else if (t < 192) sw2[t - 64] = w2[t - 64];
    else if (t < 208) sb1[t - 192] = b1[t - 192];
    else if (t < 216) sb2[t - 208] = b2[t - 208];
    if (t < 4) ssum[t] = 0;
    __syncthreads();
    int m = mask[nbq * 64 + kk];
    int ws = __reduce_add_sync(0xffffffffu, m);
    if ((t & 31) == 0) atomicAdd(&ssum[r], ws);
    __syncthreads();
    int mf = m;
    if (q == kk && ssum[r] == 0) mf = 1;

    float e0, e1, e2, e3;
    if (q == kk) { e0 = e1 = e2 = 0.f; e3 = 1.f; }
    else {
        const float* p = ef + ((size_t)nbq * 64 + kk) * 4;
        e0 = p[0]; e1 = p[1]; e2 = p[2]; e3 = p[3];
    }
    float hb[16];
    #pragma unroll
    for (int i = 0; i < 16; i++) {
        float s = sb1[i] + e0 * sw1[i] + e1 * sw1[16 + i] + e2 * sw1[32 + i] + e3 * sw1[48 + i];
        hb[i] = 0.5f * s * (1.f + erff(s * 0.70710678118654752f));
    }
    #pragma unroll
    for (int h = 0; h < 8; h++) {
        float s = sb2[h];
        #pragma unroll
        for (int i = 0; i < 16; i++) s += hb[i] * sw2[i * 8 + h];
        g_gate[h * NBLL + nbq * 64 + kk] = mf ? s : 0.f;
    }
    g_smask[nbq * 64 + kk] = e3 + (mf ? 0.f : -1e30f);
}

// ================= block mean =================
__global__ void bnode_kernel(const float* __restrict__ x)
{
    int bn = blockIdx.x, c = threadIdx.x;   // 512 threads
    const float* p = x + (size_t)bn * 64 * 512 + c;
    float s = 0.f;
    #pragma unroll 8
    for (int l = 0; l < 64; l++) s += p[l * 512];
    g_bnode[bn * 512 + c] = s * (1.f / 64.f);
}

// ================= v_block = bnode @ w_qkv[:,2C:] + b =================
__global__ void vblock_kernel(const float* __restrict__ wqkv, const float* __restrict__ bqkv)
{
    __shared__ float sA[16][512];
    int t = threadIdx.x;                 // 512
    int r0 = blockIdx.x * 16;
    for (int r = 0; r < 16; r++) sA[r][t] = g_bnode[(r0 + r) * 512 + t];
    __syncthreads();
    float acc[16];
    #pragma unroll
    for (int r = 0; r < 16; r++) acc[r] = 0.f;
    for (int k = 0; k < 512; k++) {
        float w = wqkv[(size_t)k * 1536 + 1024 + t];
        #pragma unroll
        for (int r = 0; r < 16; r++) acc[r] += sA[r][k] * w;
    }
    float bb = bqkv[1024 + t];
    #pragma unroll
    for (int r = 0; r < 16; r++) g_vblock[(r0 + r) * 512 + t] = acc[r] + bb;
}

// ================= attention per (b,nb,h) =================
__device__ __forceinline__ int swz(int row, int col) {
    return row * 64 + ((((col >> 2) ^ (row & 15)) << 2) | (col & 3));
}
__device__ __forceinline__ int swz4(int row, int c4) {
    return row * 64 + (((c4) ^ (row & 15)) << 2);
}

__global__ void __launch_bounds__(256) attn_kernel()
{
    __shared__ __align__(16) float qT[64 * 64];
    __shared__ __align__(16) float kT[64 * 64];
    __shared__ __align__(16) float vs[64 * 64];
    int tid = threadIdx.x;
    int cid = blockIdx.x;
    int h  = cid & 7;
    int bn = cid >> 3;
    int nb = bn & 511;
    int rbase = bn * 64;

    #pragma unroll
    for (int p = 0; p < 4; p++) {
        int fid = p * 256 + tid;
        int l = fid >> 4, d4 = (fid & 15) * 4;
        const float* base = g_qkv + (size_t)(rbase + l) * 1536 + h * 64 + d4;
        float4 qv = *(const float4*)(base);
        float4 kv = *(const float4*)(base + 512);
        float4 vv = *(const float4*)(base + 1024);
        qT[swz(d4 + 0, l)] = qv.x; qT[swz(d4 + 1, l)] = qv.y;
        qT[swz(d4 + 2, l)] = qv.z; qT[swz(d4 + 3, l)] = qv.w;
        kT[swz(d4 + 0, l)] = kv.x; kT[swz(d4 + 1, l)] = kv.y;
        kT[swz(d4 + 2, l)] = kv.z; kT[swz(d4 + 3, l)] = kv.w;
        *(float4*)(&vs[l * 64 + d4]) = vv;
    }
    __syncthreads();

    int tq = tid >> 4, tk = tid & 15;
    int qi0 = tq * 4, ki0 = tk * 4;

    float acc[4][4] = {};
    #pragma unroll 8
    for (int d = 0; d < 64; d++) {
        float4 a = *(const float4*)(&qT[swz4(d, tq)]);
        float4 b = *(const float4*)(&kT[swz4(d, tk)]);
        float ar[4] = {a.x, a.y, a.z, a.w};
        float br[4] = {b.x, b.y, b.z, b.w};
        #pragma unroll
        for (int i = 0; i < 4; i++)
            #pragma unroll
            for (int j = 0; j < 4; j++)
                acc[i][j] += ar[i] * br[j];
    }

    const float* smp = g_smask + nb * 4096;
    #pragma unroll
    for (int i = 0; i < 4; i++) {
        int qrow = qi0 + i;
        float s[4];
        #pragma unroll
        for (int j = 0; j < 4; j++)
            s[j] = acc[i][j] * 0.125f + smp[qrow * 64 + ki0 + j];
        float mx = fmaxf(fmaxf(s[0], s[1]), fmaxf(s[2], s[3]));
        #pragma unroll
        for (int m = 8; m; m >>= 1) mx = fmaxf(mx, __shfl_xor_sync(0xffffffffu, mx, m, 16));
        float sum = 0.f;
        #pragma unroll
        for (int j = 0; j < 4; j++) { s[j] = __expf(s[j] - mx); sum += s[j]; }
        #pragma unroll
        for (int m = 8; m; m >>= 1) sum += __shfl_xor_sync(0xffffffffu, sum, m, 16);
        float inv = 1.f / sum;
        const float* gp = g_gate + h * NBLL + nb * 4096 + qrow * 64 + ki0;
        #pragma unroll
        for (int j = 0; j < 4; j++) acc[i][j] = s[j] * inv + gp[j];
    }
    __syncthreads();
    float* ss = qT;
    #pragma unroll
    for (int i = 0; i < 4; i++)
        #pragma unroll
        for (int j = 0; j < 4; j++)
            ss[swz(ki0 + j, qi0 + i)] = acc[i][j];
    __syncthreads();

    float o[4][4] = {};
    int dj0 = tk * 4;
    #pragma unroll 8
    for (int k = 0; k < 64; k++) {
        float4 a = *(const float4*)(&ss[swz4(k, tq)]);
        float4 b = *(const float4*)(&vs[k * 64 + dj0]);
        float ar[4] = {a.x, a.y, a.z, a.w};
        float br[4] = {b.x, b.y, b.z, b.w};
        #pragma unroll
        for (int i = 0; i < 4; i++)
            #pragma unroll
            for (int j = 0; j < 4; j++)
                o[i][j] += ar[i] * br[j];
    }

    float4 vb = *(const float4*)(g_vblock + bn * 512 + h * 64 + dj0);
    #pragma unroll
    for (int i = 0; i < 4; i++) {
        int row = rbase + qi0 + i;
        float gb = g_gblock[row * 8 + h];
        float ov[4];
        ov[0] = o[i][0] + gb * vb.x;
        ov[1] = o[i][1] + gb * vb.y;
        ov[2] = o[i][2] + gb * vb.z;
        ov[3] = o[i][3] + gb * vb.w;
        __nv_bfloat16 hh[4]; __nv_bfloat16 ll[4];
        #pragma unroll
        for (int j = 0; j < 4; j++) {
            hh[j] = __float2bfloat16(ov[j]);
            ll[j] = __float2bfloat16(ov[j] - __bfloat162float(hh[j]));
        }
        __nv_bfloat162 p0; p0.x = hh[0]; p0.y = hh[1];
        __nv_bfloat162 p1; p1.x = hh[2]; p1.y = hh[3];
        __nv_bfloat162 q0; q0.x = ll[0]; q0.y = ll[1];
        __nv_bfloat162 q1; q1.x = ll[2]; q1.y = ll[3];
        size_t ofs = (size_t)row * 512 + h * 64 + dj0;
        *(__nv_bfloat162*)(g_mh + ofs) = p0; *(__nv_bfloat162*)(g_mh + ofs + 2) = p1;
        *(__nv_bfloat162*)(g_ml + ofs) = q0; *(__nv_bfloat162*)(g_ml + ofs + 2) = q1;
    }
}

// ================= launch =================
extern "C" void kernel_launch(void* const* d_in, const int* in_sizes, int n_in,
                              void* d_out, int out_size)
{
    const float* x       = (const float*)d_in[0];
    const int*   amask   = (const int*)  d_in[1];
    const float* edge    = (const float*)d_in[2];
    const float* w_qkv   = (const float*)d_in[3];
    const float* b_qkv   = (const float*)d_in[4];
    const float* w_proj  = (const float*)d_in[5];
    const float* b_proj  = (const float*)d_in[6];
    const float* w_eg1   = (const float*)d_in[7];
    const float* b_eg1   = (const float*)d_in[8];
    const float* w_eg2   = (const float*)d_in[9];
    const float* b_eg2   = (const float*)d_in[10];
    const float* w_blk   = (const float*)d_in[11];
    const float* b_blk   = (const float*)d_in[12];
    float* out = (float*)d_out;

    void *qkvp, *xh, *xl, *mh, *ml, *wqh, *wql, *wph, *wpl;
    cudaGetSymbolAddress(&qkvp, g_qkv);
    cudaGetSymbolAddress(&xh, g_xh);   cudaGetSymbolAddress(&xl, g_xl);
    cudaGetSymbolAddress(&mh, g_mh);   cudaGetSymbolAddress(&ml, g_ml);
    cudaGetSymbolAddress(&wqh, g_wqh); cudaGetSymbolAddress(&wql, g_wql);
    cudaGetSymbolAddress(&wph, g_wph); cudaGetSymbolAddress(&wpl, g_wpl);

    cudaFuncSetAttribute(gemm_bf16x2_kernel,
                         cudaFuncAttributeMaxDynamicSharedMemorySize, GSMEM);

    convx_kernel<<<MROWS / 8, 256>>>(x, w_blk, b_blk);
    wsplit_kernel<<<dim3(48, 16), 256>>>(w_qkv, (__nv_bfloat16*)wqh, (__nv_bfloat16*)wql, 512, 1536);
    wsplit_kernel<<<dim3(16, 16), 256>>>(w_proj, (__nv_bfloat16*)wph, (__nv_bfloat16*)wpl, 512, 512);
    prep_kernel  <<<NB_ * 16, 256>>>(amask, edge, w_eg1, b_eg1, w_eg2, b_eg2);
    bnode_kernel <<<BNB, 512>>>(x);
    vblock_kernel<<<64, 512>>>(w_qkv, b_qkv);

    gemm_bf16x2_kernel<<<dim3(12, 256), 256, GSMEM>>>(
        (const __nv_bfloat16*)xh, (const __nv_bfloat16*)xl,
        (const __nv_bfloat16*)wqh, (const __nv_bfloat16*)wql,
        b_qkv, (float*)qkvp, 1536);

    attn_kernel<<<BNB * H_, 256>>>();

    gemm_bf16x2_kernel<<<dim3(4, 256), 256, GSMEM>>>(
        (const __nv_bfloat16*)mh, (const __nv_bfloat16*)ml,
        (const __nv_bfloat16*)wph, (const __nv_bfloat16*)wpl,
        b_proj, out, 512);
}

// round 7
// speedup vs baseline: 1.5294x; 1.5294x over previous
#include <cuda_runtime.h>
#include <cuda_bf16.h>
#include <math.h>
#include <stdint.h>

#define B_    2
#define NB_   512
#define L_    64
#define H_    8
#define DH_   64
#define C_    512
#define C3_   1536
#define MROWS 65536          // B*NB*L
#define BNB   1024           // B*NB
#define NBLL  2097152        // NB*L*L

// ---------------- static scratch (no allocations allowed) ----------------
__device__ float g_qkv   [100663296];  // [MROWS][1536] fp32
__device__ float g_gate  [16777216];   // [H][NB][L][L]
__device__ float g_smask [2097152];    // [NB][L][L]   bias3 + (mask?0:-1e30)
__device__ float g_gblock[524288];     // [MROWS][H]
__device__ float g_vblock[524288];     // [BNB][512]
__device__ float g_bnode [524288];     // [BNB][512]
__device__ __nv_bfloat16 g_xh[33554432];   // x hi  [MROWS][512]
__device__ __nv_bfloat16 g_xl[33554432];   // x lo
__device__ __nv_bfloat16 g_mh[33554432];   // xmid hi
__device__ __nv_bfloat16 g_ml[33554432];   // xmid lo
__device__ __nv_bfloat16 g_wqh[786432];    // w_qkv^T hi [1536][512]
__device__ __nv_bfloat16 g_wql[786432];
__device__ __nv_bfloat16 g_wph[262144];    // w_proj^T hi [512][512]
__device__ __nv_bfloat16 g_wpl[262144];

// =================== PTX helpers (baseline ISA only: sm_80+) ===================
__device__ __forceinline__ uint32_t s2u(const void* p) {
    return (uint32_t)__cvta_generic_to_shared(p);
}
__device__ __forceinline__ void cp16(uint32_t dst, const void* src) {
    asm volatile("cp.async.cg.shared.global [%0], [%1], 16;" :: "r"(dst), "l"(src));
}
#define LDSM4(r, a) \
    asm volatile("ldmatrix.sync.aligned.m8n8.x4.shared.b16 {%0,%1,%2,%3}, [%4];" \
        : "=r"((r)[0]), "=r"((r)[1]), "=r"((r)[2]), "=r"((r)[3]) : "r"(a))
#define MMA16816(c, a, b) \
    asm volatile("mma.sync.aligned.m16n8k16.row.col.f32.bf16.bf16.f32 " \
        "{%0,%1,%2,%3}, {%4,%5,%6,%7}, {%8,%9}, {%0,%1,%2,%3};" \
        : "+f"((c)[0]), "+f"((c)[1]), "+f"((c)[2]), "+f"((c)[3]) \
        : "r"((a)[0]), "r"((a)[1]), "r"((a)[2]), "r"((a)[3]), "r"((b)[0]), "r"((b)[1]))

// =================== bf16x2-split GEMM via HMMA mma.sync ===================
// C[M,N] = A@W^T + bias. CTA tile 128(M) x 256(N), 512 threads (16 warps, 4Mx4N),
// warp tile 32x64 (same per-warp register footprint as the proven R5 kernel).
// K chunks of 64, double buffered. 3 passes: hi*hi + hi*lo + lo*hi, fp32 acc.
// Stage layout: Ah[128x64] Al Bh[256x64] Bl; 128B rows, XOR swizzle ch^(row&7).
#define A_TILE 16384
#define B_TILE 32768
#define STAGE_BYTES 98304
#define GSMEM (2 * STAGE_BYTES)

__device__ __forceinline__ void gemm_load_stage(
    uint32_t st, int tid, int kc,
    const __nv_bfloat16* __restrict__ A_h, const __nv_bfloat16* __restrict__ A_l,
    const __nv_bfloat16* __restrict__ B_h, const __nv_bfloat16* __restrict__ B_l)
{
    // A: 128 rows x 8 chunks = 1024 slots -> 2 iters of 512 (hi+lo)
    #pragma unroll
    for (int r = 0; r < 2; r++) {
        int idx = r * 512 + tid;
        int row = idx >> 3, ch = idx & 7;
        uint32_t d = row * 128 + ((ch ^ (row & 7)) << 4);
        cp16(st + d,          A_h + (size_t)row * 512 + kc * 64 + ch * 8);
        cp16(st + A_TILE + d, A_l + (size_t)row * 512 + kc * 64 + ch * 8);
    }
    // B: 256 rows x 8 chunks = 2048 slots -> 4 iters of 512 (hi+lo)
    #pragma unroll
    for (int r = 0; r < 4; r++) {
        int idx = r * 512 + tid;
        int row = idx >> 3, ch = idx & 7;
        uint32_t d = row * 128 + ((ch ^ (row & 7)) << 4);
        cp16(st + 2 * A_TILE + d,          B_h + (size_t)row * 512 + kc * 64 + ch * 8);
        cp16(st + 2 * A_TILE + B_TILE + d, B_l + (size_t)row * 512 + kc * 64 + ch * 8);
    }
    asm volatile("cp.async.commit_group;" ::: "memory");
}

__global__ void __launch_bounds__(512, 1)
gemm_bf16x2_kernel(const __nv_bfloat16* __restrict__ Ah, const __nv_bfloat16* __restrict__ Al,
                   const __nv_bfloat16* __restrict__ Bh, const __nv_bfloat16* __restrict__ Bl,
                   const float* __restrict__ bias, float* __restrict__ C, int ldC)
{
    extern __shared__ __align__(1024) char smem[];
    uint32_t sb = s2u(smem);
    int tid = threadIdx.x;
    int warp = tid >> 5, lane = tid & 31;
    int m0 = blockIdx.y * 128, n0 = blockIdx.x * 256;
    int wm = (warp & 3) * 32, wn = (warp >> 2) * 64;

    const __nv_bfloat16* pAh = Ah + (size_t)m0 * 512;
    const __nv_bfloat16* pAl = Al + (size_t)m0 * 512;
    const __nv_bfloat16* pBh = Bh + (size_t)n0 * 512;
    const __nv_bfloat16* pBl = Bl + (size_t)n0 * 512;

    float acc[2][8][4];
    #pragma unroll
    for (int i = 0; i < 2; i++)
        #pragma unroll
        for (int j = 0; j < 8; j++)
            #pragma unroll
            for (int t = 0; t < 4; t++) acc[i][j][t] = 0.f;

    // ldmatrix geometry (identical to R5)
    int aRow[2], bRow[4];
    #pragma unroll
    for (int mi = 0; mi < 2; mi++) aRow[mi] = wm + mi * 16 + (lane & 15);
    #pragma unroll
    for (int nj = 0; nj < 4; nj++) bRow[nj] = wn + nj * 16 + (lane & 7) + ((lane >> 4) << 3);
    int aSel = lane >> 4;          // +8 in k
    int bSel = (lane >> 3) & 1;

    gemm_load_stage(sb, tid, 0, pAh, pAl, pBh, pBl);

    for (int kc = 0; kc < 8; kc++) {
        if (kc + 1 < 8) {
            gemm_load_stage(sb + ((kc + 1) & 1) * STAGE_BYTES, tid, kc + 1,
                            pAh, pAl, pBh, pBl);
            asm volatile("cp.async.wait_group 1;" ::: "memory");
        } else {
            asm volatile("cp.async.wait_group 0;" ::: "memory");
        }
        __syncthreads();

        uint32_t stA_h = sb + (kc & 1) * STAGE_BYTES;
        uint32_t stA_l = stA_h + A_TILE;
        uint32_t stB_h = stA_h + 2 * A_TILE;
        uint32_t stB_l = stB_h + B_TILE;

        #pragma unroll
        for (int kk = 0; kk < 4; kk++) {
            // A fragments for both mi, held across the nj loop (16 regs)
            uint32_t ah[2][4], al[2][4];
            int chA = kk * 2 + aSel;
            #pragma unroll
            for (int mi = 0; mi < 2; mi++) {
                uint32_t ad = aRow[mi] * 128 + ((chA ^ (aRow[mi] & 7)) << 4);
                LDSM4(ah[mi], stA_h + ad);
                LDSM4(al[mi], stA_l + ad);
            }
            int chB = kk * 2 + bSel;
            #pragma unroll
            for (int nj = 0; nj < 4; nj++) {
                uint32_t bh[4], bl[4];
                uint32_t bd = bRow[nj] * 128 + ((chB ^ (bRow[nj] & 7)) << 4);
                LDSM4(bh, stB_h + bd);
                LDSM4(bl, stB_l + bd);
                #pragma unroll
                for (int mi = 0; mi < 2; mi++) {
                    MMA16816(acc[mi][nj * 2 + 0], ah[mi], (bh + 0));
                    MMA16816(acc[mi][nj * 2 + 1], ah[mi], (bh + 2));
                    MMA16816(acc[mi][nj * 2 + 0], ah[mi], (bl + 0));
                    MMA16816(acc[mi][nj * 2 + 1], ah[mi], (bl + 2));
                    MMA16816(acc[mi][nj * 2 + 0], al[mi], (bh + 0));
                    MMA16816(acc[mi][nj * 2 + 1], al[mi], (bh + 2));
                }
            }
        }
        __syncthreads();
    }

    // epilogue: +bias, fp32 store
    #pragma unroll
    for (int mi = 0; mi < 2; mi++) {
        int row = m0 + wm + mi * 16 + (lane >> 2);
        #pragma unroll
        for (int ni = 0; ni < 8; ni++) {
            int col = n0 + wn + ni * 8 + (lane & 3) * 2;
            float2 bv = *(const float2*)(bias + col);
            float2 o0, o1;
            o0.x = acc[mi][ni][0] + bv.x; o0.y = acc[mi][ni][1] + bv.y;
            o1.x = acc[mi][ni][2] + bv.x; o1.y = acc[mi][ni][3] + bv.y;
            *(float2*)(C + (size_t)row * ldC + col) = o0;
            *(float2*)(C + (size_t)(row + 8) * ldC + col) = o1;
        }
    }
}

// ============ convert x -> bf16 hi/lo, fused g_block sigmoid ============
__global__ void __launch_bounds__(256) convx_kernel(const float* __restrict__ x,
    const float* __restrict__ wblk, const float* __restrict__ bblk)
{
    __shared__ __align__(16) float swt[8][512];   // wblk transposed
    int tid = threadIdx.x;
    for (int idx = tid; idx < 4096; idx += 256)
        swt[idx & 7][idx >> 3] = wblk[idx];
    __syncthreads();
    int wid = tid >> 5, lane = tid & 31;
    int row = blockIdx.x * 8 + wid;
    const float* xr = x + (size_t)row * 512;
    float acc[8] = {};
    #pragma unroll
    for (int i = 0; i < 4; i++) {
        int c = i * 128 + lane * 4;
        float4 v = *(const float4*)(xr + c);
        float vv[4] = {v.x, v.y, v.z, v.w};
        __nv_bfloat16 hh[4]; __nv_bfloat16 ll[4];
        #pragma unroll
        for (int j = 0; j < 4; j++) {
            hh[j] = __float2bfloat16(vv[j]);
            ll[j] = __float2bfloat16(vv[j] - __bfloat162float(hh[j]));
        }
        __nv_bfloat162 p0; p0.x = hh[0]; p0.y = hh[1];
        __nv_bfloat162 p1; p1.x = hh[2]; p1.y = hh[3];
        __nv_bfloat162 q0; q0.x = ll[0]; q0.y = ll[1];
        __nv_bfloat162 q1; q1.x = ll[2]; q1.y = ll[3];
        size_t o = (size_t)row * 512 + c;
        *(__nv_bfloat162*)(g_xh + o) = p0; *(__nv_bfloat162*)(g_xh + o + 2) = p1;
        *(__nv_bfloat162*)(g_xl + o) = q0; *(__nv_bfloat162*)(g_xl + o + 2) = q1;
        #pragma unroll
        for (int h = 0; h < 8; h++) {
            float4 wv = *(const float4*)(&swt[h][c]);
            acc[h] += vv[0] * wv.x + vv[1] * wv.y + vv[2] * wv.z + vv[3] * wv.w;
        }
    }
    #pragma unroll
    for (int m = 16; m; m >>= 1)
        #pragma unroll
        for (int h = 0; h < 8; h++) acc[h] += __shfl_xor_sync(0xffffffffu, acc[h], m);
    if (lane == 0) {
        #pragma unroll
        for (int h = 0; h < 8; h++)
            g_gblock[row * 8 + h] = 1.f / (1.f + __expf(-(acc[h] + bblk[h])));
    }
}

// ============ weight transpose + bf16 split: W[K][N] -> T[N][K] ============
__global__ void wsplit_kernel(const float* __restrict__ W,
    __nv_bfloat16* __restrict__ Th, __nv_bfloat16* __restrict__ Tl, int Kd, int Nd)
{
    __shared__ float tile[32][33];
    int tx = threadIdx.x & 31, ty = threadIdx.x >> 5;
    int n0 = blockIdx.x * 32, k0 = blockIdx.y * 32;
    #pragma unroll
    for (int r = 0; r < 4; r++)
        tile[ty + r * 8][tx] = W[(size_t)(k0 + ty + r * 8) * Nd + n0 + tx];
    __syncthreads();
    #pragma unroll
    for (int r = 0; r < 4; r++) {
        int n = ty + r * 8;
        float v = tile[tx][n];
        __nv_bfloat16 h = __float2bfloat16(v);
        size_t o = (size_t)(n0 + n) * Kd + k0 + tx;
        Th[o] = h;
        Tl[o] = __float2bfloat16(v - __bfloat162float(h));
    }
}

// ================= prep: fixed mask, bias diag, gate MLP (R5 version) =========
__global__ void prep_kernel(const int* __restrict__ mask,
                            const float* __restrict__ ef,
                            const float* __restrict__ w1, const float* __restrict__ b1,
                            const float* __restrict__ w2, const float* __restrict__ b2)
{
    __shared__ float sw1[64], sb1[16], sw2[128], sb2[8];
    __shared__ int ssum;
    int t   = threadIdx.x;          // k index
    int nbq = blockIdx.x;           // nb*64+q
    int q   = nbq & 63;
    sw1[t] = w1[t];
    sw2[t] = w2[t]; sw2[t + 64] = w2[t + 64];
    if (t < 16) sb1[t] = b1[t];
    if (t < 8)  sb2[t] = b2[t];
    if (t == 0) ssum = 0;
    __syncthreads();
    int m = mask[nbq * 64 + t];
    atomicAdd(&ssum, m);
    __syncthreads();
    int mf = m;
    if (q == t && ssum == 0) mf = 1;

    float e0, e1, e2, e3;
    if (q == t) { e0 = e1 = e2 = 0.f; e3 = 1.f; }
    else {
        const float* p = ef + ((size_t)nbq * 64 + t) * 4;
        e0 = p[0]; e1 = p[1]; e2 = p[2]; e3 = p[3];
    }
    float hb[16];
    #pragma unroll
    for (int i = 0; i < 16; i++) {
        float s = sb1[i] + e0 * sw1[i] + e1 * sw1[16 + i] + e2 * sw1[32 + i] + e3 * sw1[48 + i];
        hb[i] = 0.5f * s * (1.f + erff(s * 0.70710678118654752f));
    }
    #pragma unroll
    for (int h = 0; h < 8; h++) {
        float s = sb2[h];
        #pragma unroll
        for (int i = 0; i < 16; i++) s += hb[i] * sw2[i * 8 + h];
        g_gate[h * NBLL + nbq * 64 + t] = mf ? s : 0.f;
    }
    g_smask[nbq * 64 + t] = e3 + (mf ? 0.f : -1e30f);
}

// ================= block mean =================
__global__ void bnode_kernel(const float* __restrict__ x)
{
    int bn = blockIdx.x, c = threadIdx.x;   // 512 threads
    const float* p = x + (size_t)bn * 64 * 512 + c;
    float s = 0.f;
    #pragma unroll 8
    for (int l = 0; l < 64; l++) s += p[l * 512];
    g_bnode[bn * 512 + c] = s * (1.f / 64.f);
}

// ================= v_block = bnode @ w_qkv[:,2C:] + b =================
__global__ void vblock_kernel(const float* __restrict__ wqkv, const float* __restrict__ bqkv)
{
    __shared__ float sA[16][512];
    int t = threadIdx.x;                 // 512
    int r0 = blockIdx.x * 16;
    for (int r = 0; r < 16; r++) sA[r][t] = g_bnode[(r0 + r) * 512 + t];
    __syncthreads();
    float acc[16];
    #pragma unroll
    for (int r = 0; r < 16; r++) acc[r] = 0.f;
    for (int k = 0; k < 512; k++) {
        float w = wqkv[(size_t)k * 1536 + 1024 + t];
        #pragma unroll
        for (int r = 0; r < 16; r++) acc[r] += sA[r][k] * w;
    }
    float bb = bqkv[1024 + t];
    #pragma unroll
    for (int r = 0; r < 16; r++) g_vblock[(r0 + r) * 512 + t] = acc[r] + bb;
}

// ================= attention per (b,nb,h) =================
__device__ __forceinline__ int swz(int row, int col) {
    return row * 64 + ((((col >> 2) ^ (row & 15)) << 2) | (col & 3));
}
__device__ __forceinline__ int swz4(int row, int c4) {
    return row * 64 + (((c4) ^ (row & 15)) << 2);
}

__global__ void __launch_bounds__(256) attn_kernel()
{
    __shared__ __align__(16) float qT[64 * 64];
    __shared__ __align__(16) float kT[64 * 64];
    __shared__ __align__(16) float vs[64 * 64];
    int tid = threadIdx.x;
    int cid = blockIdx.x;
    int h  = cid & 7;
    int bn = cid >> 3;
    int nb = bn & 511;
    int rbase = bn * 64;

    #pragma unroll
    for (int p = 0; p < 4; p++) {
        int fid = p * 256 + tid;
        int l = fid >> 4, d4 = (fid & 15) * 4;
        const float* base = g_qkv + (size_t)(rbase + l) * 1536 + h * 64 + d4;
        float4 qv = *(const float4*)(base);
        float4 kv = *(const float4*)(base + 512);
        float4 vv = *(const float4*)(base + 1024);
        qT[swz(d4 + 0, l)] = qv.x; qT[swz(d4 + 1, l)] = qv.y;
        qT[swz(d4 + 2, l)] = qv.z; qT[swz(d4 + 3, l)] = qv.w;
        kT[swz(d4 + 0, l)] = kv.x; kT[swz(d4 + 1, l)] = kv.y;
        kT[swz(d4 + 2, l)] = kv.z; kT[swz(d4 + 3, l)] = kv.w;
        *(float4*)(&vs[l * 64 + d4]) = vv;
    }
    __syncthreads();

    int tq = tid >> 4, tk = tid & 15;
    int qi0 = tq * 4, ki0 = tk * 4;

    float acc[4][4] = {};
    #pragma unroll 8
    for (int d = 0; d < 64; d++) {
        float4 a = *(const float4*)(&qT[swz4(d, tq)]);
        float4 b = *(const float4*)(&kT[swz4(d, tk)]);
        float ar[4] = {a.x, a.y, a.z, a.w};
        float br[4] = {b.x, b.y, b.z, b.w};
        #pragma unroll
        for (int i = 0; i < 4; i++)
            #pragma unroll
            for (int j = 0; j < 4; j++)
                acc[i][j] += ar[i] * br[j];
    }

    const float* smp = g_smask + nb * 4096;
    #pragma unroll
    for (int i = 0; i < 4; i++) {
        int qrow = qi0 + i;
        float s[4];
        #pragma unroll
        for (int j = 0; j < 4; j++)
            s[j] = acc[i][j] * 0.125f + smp[qrow * 64 + ki0 + j];
        float mx = fmaxf(fmaxf(s[0], s[1]), fmaxf(s[2], s[3]));
        #pragma unroll
        for (int m = 8; m; m >>= 1) mx = fmaxf(mx, __shfl_xor_sync(0xffffffffu, mx, m, 16));
        float sum = 0.f;
        #pragma unroll
        for (int j = 0; j < 4; j++) { s[j] = __expf(s[j] - mx); sum += s[j]; }
        #pragma unroll
        for (int m = 8; m; m >>= 1) sum += __shfl_xor_sync(0xffffffffu, sum, m, 16);
        float inv = 1.f / sum;
        const float* gp = g_gate + h * NBLL + nb * 4096 + qrow * 64 + ki0;
        #pragma unroll
        for (int j = 0; j < 4; j++) acc[i][j] = s[j] * inv + gp[j];
    }
    __syncthreads();
    float* ss = qT;
    #pragma unroll
    for (int i = 0; i < 4; i++)
        #pragma unroll
        for (int j = 0; j < 4; j++)
            ss[swz(ki0 + j, qi0 + i)] = acc[i][j];
    __syncthreads();

    float o[4][4] = {};
    int dj0 = tk * 4;
    #pragma unroll 8
    for (int k = 0; k < 64; k++) {
        float4 a = *(const float4*)(&ss[swz4(k, tq)]);
        float4 b = *(const float4*)(&vs[k * 64 + dj0]);
        float ar[4] = {a.x, a.y, a.z, a.w};
        float br[4] = {b.x, b.y, b.z, b.w};
        #pragma unroll
        for (int i = 0; i < 4; i++)
            #pragma unroll
            for (int j = 0; j < 4; j++)
                o[i][j] += ar[i] * br[j];
    }

    float4 vb = *(const float4*)(g_vblock + bn * 512 + h * 64 + dj0);
    #pragma unroll
    for (int i = 0; i < 4; i++) {
        int row = rbase + qi0 + i;
        float gb = g_gblock[row * 8 + h];
        float ov[4];
        ov[0] = o[i][0] + gb * vb.x;
        ov[1] = o[i][1] + gb * vb.y;
        ov[2] = o[i][2] + gb * vb.z;
        ov[3] = o[i][3] + gb * vb.w;
        __nv_bfloat16 hh[4]; __nv_bfloat16 ll[4];
        #pragma unroll
        for (int j = 0; j < 4; j++) {
            hh[j] = __float2bfloat16(ov[j]);
            ll[j] = __float2bfloat16(ov[j] - __bfloat162float(hh[j]));
        }
        __nv_bfloat162 p0; p0.x = hh[0]; p0.y = hh[1];
        __nv_bfloat162 p1; p1.x = hh[2]; p1.y = hh[3];
        __nv_bfloat162 q0; q0.x = ll[0]; q0.y = ll[1];
        __nv_bfloat162 q1; q1.x = ll[2]; q1.y = ll[3];
        size_t ofs = (size_t)row * 512 + h * 64 + dj0;
        *(__nv_bfloat162*)(g_mh + ofs) = p0; *(__nv_bfloat162*)(g_mh + ofs + 2) = p1;
        *(__nv_bfloat162*)(g_ml + ofs) = q0; *(__nv_bfloat162*)(g_ml + ofs + 2) = q1;
    }
}

// ================= launch =================
extern "C" void kernel_launch(void* const* d_in, const int* in_sizes, int n_in,
                              void* d_out, int out_size)
{
    const float* x       = (const float*)d_in[0];
    const int*   amask   = (const int*)  d_in[1];
    const float* edge    = (const float*)d_in[2];
    const float* w_qkv   = (const float*)d_in[3];
    const float* b_qkv   = (const float*)d_in[4];
    const float* w_proj  = (const float*)d_in[5];
    const float* b_proj  = (const float*)d_in[6];
    const float* w_eg1   = (const float*)d_in[7];
    const float* b_eg1   = (const float*)d_in[8];
    const float* w_eg2   = (const float*)d_in[9];
    const float* b_eg2   = (const float*)d_in[10];
    const float* w_blk   = (const float*)d_in[11];
    const float* b_blk   = (const float*)d_in[12];
    float* out = (float*)d_out;

    void *qkvp, *xh, *xl, *mh, *ml, *wqh, *wql, *wph, *wpl;
    cudaGetSymbolAddress(&qkvp, g_qkv);
    cudaGetSymbolAddress(&xh, g_xh);   cudaGetSymbolAddress(&xl, g_xl);
    cudaGetSymbolAddress(&mh, g_mh);   cudaGetSymbolAddress(&ml, g_ml);
    cudaGetSymbolAddress(&wqh, g_wqh); cudaGetSymbolAddress(&wql, g_wql);
    cudaGetSymbolAddress(&wph, g_wph); cudaGetSymbolAddress(&wpl, g_wpl);

    cudaFuncSetAttribute(gemm_bf16x2_kernel,
                         cudaFuncAttributeMaxDynamicSharedMemorySize, GSMEM);

    convx_kernel<<<MROWS / 8, 256>>>(x, w_blk, b_blk);
    wsplit_kernel<<<dim3(48, 16), 256>>>(w_qkv, (__nv_bfloat16*)wqh, (__nv_bfloat16*)wql, 512, 1536);
    wsplit_kernel<<<dim3(16, 16), 256>>>(w_proj, (__nv_bfloat16*)wph, (__nv_bfloat16*)wpl, 512, 512);
    prep_kernel  <<<NB_ * 64, 64>>>(amask, edge, w_eg1, b_eg1, w_eg2, b_eg2);
    bnode_kernel <<<BNB, 512>>>(x);
    vblock_kernel<<<64, 512>>>(w_qkv, b_qkv);

    gemm_bf16x2_kernel<<<dim3(6, 512), 512, GSMEM>>>(
        (const __nv_bfloat16*)xh, (const __nv_bfloat16*)xl,
        (const __nv_bfloat16*)wqh, (const __nv_bfloat16*)wql,
        b_qkv, (float*)qkvp, 1536);

    attn_kernel<<<BNB * H_, 256>>>();

    gemm_bf16x2_kernel<<<dim3(2, 512), 512, GSMEM>>>(
        (const __nv_bfloat16*)mh, (const __nv_bfloat16*)ml,
        (const __nv_bfloat16*)wph, (const __nv_bfloat16*)wpl,
        b_proj, out, 512);
}

// round 8
// speedup vs baseline: 2.2671x; 1.4823x over previous
#include <cuda_runtime.h>
#include <cuda_bf16.h>
#include <cuda_fp16.h>
#include <math.h>
#include <stdint.h>

#define B_    2
#define NB_   512
#define L_    64
#define H_    8
#define DH_   64
#define C_    512
#define C3_   1536
#define MROWS 65536          // B*NB*L
#define BNB   1024           // B*NB
#define NBLL  2097152        // NB*L*L

// ---------------- static scratch (no allocations allowed) ----------------
__device__ float g_qkv   [100663296];  // [MROWS][1536] fp32
__device__ float g_gate  [16777216];   // [H][NB][L][L]
__device__ float g_smask [2097152];    // [NB][L][L]   bias3 + (mask?0:-1e30)
__device__ float g_gblock[524288];     // [MROWS][H]
__device__ float g_vblock[524288];     // [BNB][512]
__device__ float g_bnode [524288];     // [BNB][512]
__device__ __half g_xq[33554432];      // x fp16 [MROWS][512]
__device__ __half g_mq[33554432];      // xmid fp16
__device__ __half g_wq[786432];        // w_qkv^T fp16 [1536][512]
__device__ __half g_wp[262144];        // w_proj^T fp16 [512][512]

// =================== PTX helpers (baseline ISA only: sm_80+) ===================
__device__ __forceinline__ uint32_t s2u(const void* p) {
    return (uint32_t)__cvta_generic_to_shared(p);
}
__device__ __forceinline__ void cp16(uint32_t dst, const void* src) {
    asm volatile("cp.async.cg.shared.global [%0], [%1], 16;" :: "r"(dst), "l"(src));
}
#define LDSM4(r, a) \
    asm volatile("ldmatrix.sync.aligned.m8n8.x4.shared.b16 {%0,%1,%2,%3}, [%4];" \
        : "=r"((r)[0]), "=r"((r)[1]), "=r"((r)[2]), "=r"((r)[3]) : "r"(a))
#define MMA16816H(c, a, b) \
    asm volatile("mma.sync.aligned.m16n8k16.row.col.f32.f16.f16.f32 " \
        "{%0,%1,%2,%3}, {%4,%5,%6,%7}, {%8,%9}, {%0,%1,%2,%3};" \
        : "+f"((c)[0]), "+f"((c)[1]), "+f"((c)[2]), "+f"((c)[3]) \
        : "r"((a)[0]), "r"((a)[1]), "r"((a)[2]), "r"((a)[3]), "r"((b)[0]), "r"((b)[1]))

// =================== fp16 single-pass GEMM via HMMA mma.sync ===================
// C[M,N] = A@W^T + bias. CTA 128(M) x 256(N), 512 threads (16 warps 4Mx4N),
// warp tile 32x64. K chunks of 64, double buffered.
// Stage: A[128x64] fp16 (16KB) + B[256x64] fp16 (32KB); 128B rows, XOR swizzle.
#define A_TILE 16384
#define B_TILE 32768
#define STAGE_BYTES 49152
#define GSMEM (2 * STAGE_BYTES)

__device__ __forceinline__ void gemm_load_stage(
    uint32_t st, int tid, int kc,
    const __half* __restrict__ A, const __half* __restrict__ Bm)
{
    // A: 128 rows x 8 chunks = 1024 slots -> 2 iters of 512
    #pragma unroll
    for (int r = 0; r < 2; r++) {
        int idx = r * 512 + tid;
        int row = idx >> 3, ch = idx & 7;
        uint32_t d = row * 128 + ((ch ^ (row & 7)) << 4);
        cp16(st + d, A + (size_t)row * 512 + kc * 64 + ch * 8);
    }
    // B: 256 rows x 8 chunks = 2048 slots -> 4 iters of 512
    #pragma unroll
    for (int r = 0; r < 4; r++) {
        int idx = r * 512 + tid;
        int row = idx >> 3, ch = idx & 7;
        uint32_t d = row * 128 + ((ch ^ (row & 7)) << 4);
        cp16(st + A_TILE + d, Bm + (size_t)row * 512 + kc * 64 + ch * 8);
    }
    asm volatile("cp.async.commit_group;" ::: "memory");
}

__global__ void __launch_bounds__(512, 1)
gemm_fp16_kernel(const __half* __restrict__ A, const __half* __restrict__ Bm,
                 const float* __restrict__ bias, float* __restrict__ C, int ldC)
{
    extern __shared__ __align__(1024) char smem[];
    uint32_t sb = s2u(smem);
    int tid = threadIdx.x;
    int warp = tid >> 5, lane = tid & 31;
    int m0 = blockIdx.y * 128, n0 = blockIdx.x * 256;
    int wm = (warp & 3) * 32, wn = (warp >> 2) * 64;

    const __half* pA = A + (size_t)m0 * 512;
    const __half* pB = Bm + (size_t)n0 * 512;

    float acc[2][8][4];
    #pragma unroll
    for (int i = 0; i < 2; i++)
        #pragma unroll
        for (int j = 0; j < 8; j++)
            #pragma unroll
            for (int t = 0; t < 4; t++) acc[i][j][t] = 0.f;

    int aRow[2], bRow[4];
    #pragma unroll
    for (int mi = 0; mi < 2; mi++) aRow[mi] = wm + mi * 16 + (lane & 15);
    #pragma unroll
    for (int nj = 0; nj < 4; nj++) bRow[nj] = wn + nj * 16 + (lane & 7) + ((lane >> 4) << 3);
    int aSel = lane >> 4;
    int bSel = (lane >> 3) & 1;

    gemm_load_stage(sb, tid, 0, pA, pB);

    for (int kc = 0; kc < 8; kc++) {
        if (kc + 1 < 8) {
            gemm_load_stage(sb + ((kc + 1) & 1) * STAGE_BYTES, tid, kc + 1, pA, pB);
            asm volatile("cp.async.wait_group 1;" ::: "memory");
        } else {
            asm volatile("cp.async.wait_group 0;" ::: "memory");
        }
        __syncthreads();

        uint32_t stA = sb + (kc & 1) * STAGE_BYTES;
        uint32_t stB = stA + A_TILE;

        #pragma unroll
        for (int kk = 0; kk < 4; kk++) {
            uint32_t af[2][4];
            int chA = kk * 2 + aSel;
            #pragma unroll
            for (int mi = 0; mi < 2; mi++) {
                uint32_t ad = aRow[mi] * 128 + ((chA ^ (aRow[mi] & 7)) << 4);
                LDSM4(af[mi], stA + ad);
            }
            int chB = kk * 2 + bSel;
            #pragma unroll
            for (int nj = 0; nj < 4; nj++) {
                uint32_t bf[4];
                uint32_t bd = bRow[nj] * 128 + ((chB ^ (bRow[nj] & 7)) << 4);
                LDSM4(bf, stB + bd);
                #pragma unroll
                for (int mi = 0; mi < 2; mi++) {
                    MMA16816H(acc[mi][nj * 2 + 0], af[mi], (bf + 0));
                    MMA16816H(acc[mi][nj * 2 + 1], af[mi], (bf + 2));
                }
            }
        }
        __syncthreads();
    }

    // epilogue: +bias, fp32 store
    #pragma unroll
    for (int mi = 0; mi < 2; mi++) {
        int row = m0 + wm + mi * 16 + (lane >> 2);
        #pragma unroll
        for (int ni = 0; ni < 8; ni++) {
            int col = n0 + wn + ni * 8 + (lane & 3) * 2;
            float2 bv = *(const float2*)(bias + col);
            float2 o0, o1;
            o0.x = acc[mi][ni][0] + bv.x; o0.y = acc[mi][ni][1] + bv.y;
            o1.x = acc[mi][ni][2] + bv.x; o1.y = acc[mi][ni][3] + bv.y;
            *(float2*)(C + (size_t)row * ldC + col) = o0;
            *(float2*)(C + (size_t)(row + 8) * ldC + col) = o1;
        }
    }
}

// ============ convert x -> fp16, fused g_block sigmoid ============
__global__ void __launch_bounds__(256) convx_kernel(const float* __restrict__ x,
    const float* __restrict__ wblk, const float* __restrict__ bblk)
{
    __shared__ __align__(16) float swt[8][512];   // wblk transposed
    int tid = threadIdx.x;
    for (int idx = tid; idx < 4096; idx += 256)
        swt[idx & 7][idx >> 3] = wblk[idx];
    __syncthreads();
    int wid = tid >> 5, lane = tid & 31;
    int row = blockIdx.x * 8 + wid;
    const float* xr = x + (size_t)row * 512;
    float acc[8] = {};
    #pragma unroll
    for (int i = 0; i < 4; i++) {
        int c = i * 128 + lane * 4;
        float4 v = *(const float4*)(xr + c);
        __half2 h0 = __floats2half2_rn(v.x, v.y);
        __half2 h1 = __floats2half2_rn(v.z, v.w);
        size_t o = (size_t)row * 512 + c;
        *(__half2*)(g_xq + o) = h0; *(__half2*)(g_xq + o + 2) = h1;
        #pragma unroll
        for (int h = 0; h < 8; h++) {
            float4 wv = *(const float4*)(&swt[h][c]);
            acc[h] += v.x * wv.x + v.y * wv.y + v.z * wv.z + v.w * wv.w;
        }
    }
    #pragma unroll
    for (int m = 16; m; m >>= 1)
        #pragma unroll
        for (int h = 0; h < 8; h++) acc[h] += __shfl_xor_sync(0xffffffffu, acc[h], m);
    if (lane == 0) {
        #pragma unroll
        for (int h = 0; h < 8; h++)
            g_gblock[row * 8 + h] = 1.f / (1.f + __expf(-(acc[h] + bblk[h])));
    }
}

// ============ weight transpose + fp16: W[K][N] -> T[N][K] ============
__global__ void wsplit_kernel(const float* __restrict__ W,
    __half* __restrict__ T, int Kd, int Nd)
{
    __shared__ float tile[32][33];
    int tx = threadIdx.x & 31, ty = threadIdx.x >> 5;
    int n0 = blockIdx.x * 32, k0 = blockIdx.y * 32;
    #pragma unroll
    for (int r = 0; r < 4; r++)
        tile[ty + r * 8][tx] = W[(size_t)(k0 + ty + r * 8) * Nd + n0 + tx];
    __syncthreads();
    #pragma unroll
    for (int r = 0; r < 4; r++) {
        int n = ty + r * 8;
        T[(size_t)(n0 + n) * Kd + k0 + tx] = __float2half_rn(tile[tx][n]);
    }
}

// ================= prep: fixed mask, bias diag, gate MLP =================
__global__ void prep_kernel(const int* __restrict__ mask,
                            const float* __restrict__ ef,
                            const float* __restrict__ w1, const float* __restrict__ b1,
                            const float* __restrict__ w2, const float* __restrict__ b2)
{
    __shared__ float sw1[64], sb1[16], sw2[128], sb2[8];
    __shared__ int ssum;
    int t   = threadIdx.x;          // k index
    int nbq = blockIdx.x;           // nb*64+q
    int q   = nbq & 63;
    sw1[t] = w1[t];
    sw2[t] = w2[t]; sw2[t + 64] = w2[t + 64];
    if (t < 16) sb1[t] = b1[t];
    if (t < 8)  sb2[t] = b2[t];
    if (t == 0) ssum = 0;
    __syncthreads();
    int m = mask[nbq * 64 + t];
    atomicAdd(&ssum, m);
    __syncthreads();
    int mf = m;
    if (q == t && ssum == 0) mf = 1;

    float e0, e1, e2, e3;
    if (q == t) { e0 = e1 = e2 = 0.f; e3 = 1.f; }
    else {
        const float* p = ef + ((size_t)nbq * 64 + t) * 4;
        e0 = p[0]; e1 = p[1]; e2 = p[2]; e3 = p[3];
    }
    float hb[16];
    #pragma unroll
    for (int i = 0; i < 16; i++) {
        float s = sb1[i] + e0 * sw1[i] + e1 * sw1[16 + i] + e2 * sw1[32 + i] + e3 * sw1[48 + i];
        hb[i] = 0.5f * s * (1.f + erff(s * 0.70710678118654752f));
    }
    #pragma unroll
    for (int h = 0; h < 8; h++) {
        float s = sb2[h];
        #pragma unroll
        for (int i = 0; i < 16; i++) s += hb[i] * sw2[i * 8 + h];
        g_gate[h * NBLL + nbq * 64 + t] = mf ? s : 0.f;
    }
    g_smask[nbq * 64 + t] = e3 + (mf ? 0.f : -1e30f);
}

// ================= block mean =================
__global__ void bnode_kernel(const float* __restrict__ x)
{
    int bn = blockIdx.x, c = threadIdx.x;   // 512 threads
    const float* p = x + (size_t)bn * 64 * 512 + c;
    float s = 0.f;
    #pragma unroll 8
    for (int l = 0; l < 64; l++) s += p[l * 512];
    g_bnode[bn * 512 + c] = s * (1.f / 64.f);
}

// ================= v_block = bnode @ w_qkv[:,2C:] + b =================
__global__ void vblock_kernel(const float* __restrict__ wqkv, const float* __restrict__ bqkv)
{
    __shared__ float sA[16][512];
    int t = threadIdx.x;                 // 512
    int r0 = blockIdx.x * 16;
    for (int r = 0; r < 16; r++) sA[r][t] = g_bnode[(r0 + r) * 512 + t];
    __syncthreads();
    float acc[16];
    #pragma unroll
    for (int r = 0; r < 16; r++) acc[r] = 0.f;
    for (int k = 0; k < 512; k++) {
        float w = wqkv[(size_t)k * 1536 + 1024 + t];
        #pragma unroll
        for (int r = 0; r < 16; r++) acc[r] += sA[r][k] * w;
    }
    float bb = bqkv[1024 + t];
    #pragma unroll
    for (int r = 0; r < 16; r++) g_vblock[(r0 + r) * 512 + t] = acc[r] + bb;
}

// ================= attention per (b,nb,h) =================
__device__ __forceinline__ int swz(int row, int col) {
    return row * 64 + ((((col >> 2) ^ (row & 15)) << 2) | (col & 3));
}
__device__ __forceinline__ int swz4(int row, int c4) {
    return row * 64 + (((c4) ^ (row & 15)) << 2);
}

__global__ void __launch_bounds__(256) attn_kernel()
{
    __shared__ __align__(16) float qT[64 * 64];
    __shared__ __align__(16) float kT[64 * 64];
    __shared__ __align__(16) float vs[64 * 64];
    int tid = threadIdx.x;
    int cid = blockIdx.x;
    int h  = cid & 7;
    int bn = cid >> 3;
    int nb = bn & 511;
    int rbase = bn * 64;

    #pragma unroll
    for (int p = 0; p < 4; p++) {
        int fid = p * 256 + tid;
        int l = fid >> 4, d4 = (fid & 15) * 4;
        const float* base = g_qkv + (size_t)(rbase + l) * 1536 + h * 64 + d4;
        float4 qv = *(const float4*)(base);
        float4 kv = *(const float4*)(base + 512);
        float4 vv = *(const float4*)(base + 1024);
        qT[swz(d4 + 0, l)] = qv.x; qT[swz(d4 + 1, l)] = qv.y;
        qT[swz(d4 + 2, l)] = qv.z; qT[swz(d4 + 3, l)] = qv.w;
        kT[swz(d4 + 0, l)] = kv.x; kT[swz(d4 + 1, l)] = kv.y;
        kT[swz(d4 + 2, l)] = kv.z; kT[swz(d4 + 3, l)] = kv.w;
        *(float4*)(&vs[l * 64 + d4]) = vv;
    }
    __syncthreads();

    int tq = tid >> 4, tk = tid & 15;
    int qi0 = tq * 4, ki0 = tk * 4;

    float acc[4][4] = {};
    #pragma unroll 8
    for (int d = 0; d < 64; d++) {
        float4 a = *(const float4*)(&qT[swz4(d, tq)]);
        float4 b = *(const float4*)(&kT[swz4(d, tk)]);
        float ar[4] = {a.x, a.y, a.z, a.w};
        float br[4] = {b.x, b.y, b.z, b.w};
        #pragma unroll
        for (int i = 0; i < 4; i++)
            #pragma unroll
            for (int j = 0; j < 4; j++)
                acc[i][j] += ar[i] * br[j];
    }

    const float* smp = g_smask + nb * 4096;
    #pragma unroll
    for (int i = 0; i < 4; i++) {
        int qrow = qi0 + i;
        float s[4];
        #pragma unroll
        for (int j = 0; j < 4; j++)
            s[j] = acc[i][j] * 0.125f + smp[qrow * 64 + ki0 + j];
        float mx = fmaxf(fmaxf(s[0], s[1]), fmaxf(s[2], s[3]));
        #pragma unroll
        for (int m = 8; m; m >>= 1) mx = fmaxf(mx, __shfl_xor_sync(0xffffffffu, mx, m, 16));
        float sum = 0.f;
        #pragma unroll
        for (int j = 0; j < 4; j++) { s[j] = __expf(s[j] - mx); sum += s[j]; }
        #pragma unroll
        for (int m = 8; m; m >>= 1) sum += __shfl_xor_sync(0xffffffffu, sum, m, 16);
        float inv = 1.f / sum;
        const float* gp = g_gate + h * NBLL + nb * 4096 + qrow * 64 + ki0;
        #pragma unroll
        for (int j = 0; j < 4; j++) acc[i][j] = s[j] * inv + gp[j];
    }
    __syncthreads();
    float* ss = qT;
    #pragma unroll
    for (int i = 0; i < 4; i++)
        #pragma unroll
        for (int j = 0; j < 4; j++)
            ss[swz(ki0 + j, qi0 + i)] = acc[i][j];
    __syncthreads();

    float o[4][4] = {};
    int dj0 = tk * 4;
    #pragma unroll 8
    for (int k = 0; k < 64; k++) {
        float4 a = *(const float4*)(&ss[swz4(k, tq)]);
        float4 b = *(const float4*)(&vs[k * 64 + dj0]);
        float ar[4] = {a.x, a.y, a.z, a.w};
        float br[4] = {b.x, b.y, b.z, b.w};
        #pragma unroll
        for (int i = 0; i < 4; i++)
            #pragma unroll
            for (int j = 0; j < 4; j++)
                o[i][j] += ar[i] * br[j];
    }

    float4 vb = *(const float4*)(g_vblock + bn * 512 + h * 64 + dj0);
    #pragma unroll
    for (int i = 0; i < 4; i++) {
        int row = rbase + qi0 + i;
        float gb = g_gblock[row * 8 + h];
        __half2 h0 = __floats2half2_rn(o[i][0] + gb * vb.x, o[i][1] + gb * vb.y);
        __half2 h1 = __floats2half2_rn(o[i][2] + gb * vb.z, o[i][3] + gb * vb.w);
        size_t ofs = (size_t)row * 512 + h * 64 + dj0;
        *(__half2*)(g_mq + ofs) = h0; *(__half2*)(g_mq + ofs + 2) = h1;
    }
}

// ================= launch =================
extern "C" void kernel_launch(void* const* d_in, const int* in_sizes, int n_in,
                              void* d_out, int out_size)
{
    const float* x       = (const float*)d_in[0];
    const int*   amask   = (const int*)  d_in[1];
    const float* edge    = (const float*)d_in[2];
    const float* w_qkv   = (const float*)d_in[3];
    const float* b_qkv   = (const float*)d_in[4];
    const float* w_proj  = (const float*)d_in[5];
    const float* b_proj  = (const float*)d_in[6];
    const float* w_eg1   = (const float*)d_in[7];
    const float* b_eg1   = (const float*)d_in[8];
    const float* w_eg2   = (const float*)d_in[9];
    const float* b_eg2   = (const float*)d_in[10];
    const float* w_blk   = (const float*)d_in[11];
    const float* b_blk   = (const float*)d_in[12];
    float* out = (float*)d_out;

    void *qkvp, *xq, *mq, *wq, *wp;
    cudaGetSymbolAddress(&qkvp, g_qkv);
    cudaGetSymbolAddress(&xq, g_xq);
    cudaGetSymbolAddress(&mq, g_mq);
    cudaGetSymbolAddress(&wq, g_wq);
    cudaGetSymbolAddress(&wp, g_wp);

    cudaFuncSetAttribute(gemm_fp16_kernel,
                         cudaFuncAttributeMaxDynamicSharedMemorySize, GSMEM);

    convx_kernel<<<MROWS / 8, 256>>>(x, w_blk, b_blk);
    wsplit_kernel<<<dim3(48, 16), 256>>>(w_qkv, (__half*)wq, 512, 1536);
    wsplit_kernel<<<dim3(16, 16), 256>>>(w_proj, (__half*)wp, 512, 512);
    prep_kernel  <<<NB_ * 64, 64>>>(amask, edge, w_eg1, b_eg1, w_eg2, b_eg2);
    bnode_kernel <<<BNB, 512>>>(x);
    vblock_kernel<<<64, 512>>>(w_qkv, b_qkv);

    gemm_fp16_kernel<<<dim3(6, 512), 512, GSMEM>>>(
        (const __half*)xq, (const __half*)wq, b_qkv, (float*)qkvp, 1536);

    attn_kernel<<<BNB * H_, 256>>>();

    gemm_fp16_kernel<<<dim3(2, 512), 512, GSMEM>>>(
        (const __half*)mq, (const __half*)wp, b_proj, out, 512);
}